// round 7
// baseline (speedup 1.0000x reference)
#include <cuda_runtime.h>
#include <cuda_bf16.h>
#include <math.h>

#define BB 8
#define NN 4096
#define MM 4096
#define DD 128
#define NTILES 32          // 4096 / 128 tiles along each reduced dim

// ---------------- scratch (device globals: no allocation allowed) ----------
__device__ float g_d0n[BB * NN * DD];   // normalized descriptors0
__device__ float g_d1n[BB * MM * DD];   // normalized descriptors1

// per-tile partial top-2: [row/col global id][tile] -> (v0,v1) + (i0,i1)
__device__ float2 g_rp_v[BB * NN * NTILES];
__device__ int2   g_rp_i[BB * NN * NTILES];
__device__ float2 g_cp_v[BB * MM * NTILES];
__device__ int2   g_cp_i[BB * MM * NTILES];

__device__ int    g_m0raw[BB * NN];     // pre-mutual matches
__device__ int    g_m1raw[BB * MM];

// ---------------- helpers --------------------------------------------------
__device__ __forceinline__ void push2(float v, int i,
                                      float& v0, int& i0, float& v1, int& i1) {
    if (v > v0) { v1 = v0; i1 = i0; v0 = v; i0 = i; }
    else if (v > v1) { v1 = v; i1 = i; }
}

__device__ __forceinline__ bool better(float va, int ia, float vb, int ib) {
    return (va > vb) || (va == vb && ia < ib);
}

__device__ __forceinline__ void merge2(float& v0, int& i0, float& v1, int& i1,
                                       float ov0, int oi0, float ov1, int oi1) {
    if (better(ov0, oi0, v0, i0)) {
        if (better(v0, i0, ov1, oi1)) { v1 = v0; i1 = i0; }
        else                          { v1 = ov1; i1 = oi1; }
        v0 = ov0; i0 = oi0;
    } else {
        if (better(ov0, oi0, v1, i1)) { v1 = ov0; i1 = oi0; }
    }
}

// ---------------- 1. normalize ---------------------------------------------
__global__ void normalize_k(const float* __restrict__ d0,
                            const float* __restrict__ d1) {
    int warp = (blockIdx.x * blockDim.x + threadIdx.x) >> 5;
    int lane = threadIdx.x & 31;
    const int total = BB * NN + BB * MM;
    if (warp >= total) return;

    const float* src;
    float* dst;
    if (warp < BB * NN) {
        src = d0 + (size_t)warp * DD;
        dst = g_d0n + (size_t)warp * DD;
    } else {
        int w = warp - BB * NN;
        src = d1 + (size_t)w * DD;
        dst = g_d1n + (size_t)w * DD;
    }

    float4 v = *(const float4*)(src + lane * 4);
    float s = v.x * v.x + v.y * v.y + v.z * v.z + v.w * v.w;
#pragma unroll
    for (int off = 16; off > 0; off >>= 1)
        s += __shfl_xor_sync(0xFFFFFFFFu, s, off);
    float inv = 1.0f / fmaxf(sqrtf(s), 1e-12f);
    v.x *= inv; v.y *= inv; v.z *= inv; v.w *= inv;
    *(float4*)(dst + lane * 4) = v;
}

// ---------------- 2. SGEMM + fused top-2 partials ----------------------------
// tile 128x128, BK=16, 256 threads, TM=TN=8.
// Epilogue: row partial top-2 (shfl over tcol), col partial top-2 (smem over trow).
#define BK 16
#define LDSM 132   // padded row length for smem tiles

__global__ __launch_bounds__(256)
void gemm_k(float* __restrict__ C) {
    // union: A/B tiles during mainloop, col-reduction buffer in epilogue
    __shared__ float4 shbuf[16 * 128];            // 32 KB
    float* As = (float*)shbuf;                     // BK*LDSM floats
    float* Bs = As + BK * LDSM;                    // BK*LDSM floats (total 16896 B)

    const int b  = blockIdx.z;
    const int n0 = blockIdx.y * 128;
    const int m0 = blockIdx.x * 128;
    const int tileM = blockIdx.x;                  // column-tile index (0..31)
    const int tileN = blockIdx.y;                  // row-tile index    (0..31)

    const float* __restrict__ Ab = g_d0n + ((size_t)b * NN + n0) * DD;
    const float* __restrict__ Bb = g_d1n + ((size_t)b * MM + m0) * DD;
    float* __restrict__ Cb = C + (size_t)b * NN * MM + (size_t)n0 * MM + m0;

    const int tid  = threadIdx.x;
    const int tcol = tid & 15;   // 0..15
    const int trow = tid >> 4;   // 0..15

    float acc[8][8];
#pragma unroll
    for (int i = 0; i < 8; i++)
#pragma unroll
        for (int j = 0; j < 8; j++) acc[i][j] = 0.0f;

    for (int k0 = 0; k0 < DD; k0 += BK) {
#pragma unroll
        for (int it = 0; it < 2; it++) {
            int f   = tid + it * 256;
            int row = f >> 2;
            int cv  = (f & 3) * 4;
            float4 av = *(const float4*)(Ab + (size_t)row * DD + k0 + cv);
            As[(cv + 0) * LDSM + row] = av.x;
            As[(cv + 1) * LDSM + row] = av.y;
            As[(cv + 2) * LDSM + row] = av.z;
            As[(cv + 3) * LDSM + row] = av.w;
            float4 bv = *(const float4*)(Bb + (size_t)row * DD + k0 + cv);
            Bs[(cv + 0) * LDSM + row] = bv.x;
            Bs[(cv + 1) * LDSM + row] = bv.y;
            Bs[(cv + 2) * LDSM + row] = bv.z;
            Bs[(cv + 3) * LDSM + row] = bv.w;
        }
        __syncthreads();

#pragma unroll
        for (int kk = 0; kk < BK; kk++) {
            float a[8], bb[8];
#pragma unroll
            for (int i = 0; i < 8; i++) a[i]  = As[kk * LDSM + trow * 8 + i];
#pragma unroll
            for (int j = 0; j < 8; j++) bb[j] = Bs[kk * LDSM + tcol * 8 + j];
#pragma unroll
            for (int i = 0; i < 8; i++)
#pragma unroll
                for (int j = 0; j < 8; j++)
                    acc[i][j] = fmaf(a[i], bb[j], acc[i][j]);
        }
        __syncthreads();
    }

    // ---- write sim tile ----
#pragma unroll
    for (int i = 0; i < 8; i++) {
        size_t rowoff = (size_t)(trow * 8 + i) * MM + tcol * 8;
        *(float4*)(Cb + rowoff)     = make_float4(acc[i][0], acc[i][1], acc[i][2], acc[i][3]);
        *(float4*)(Cb + rowoff + 4) = make_float4(acc[i][4], acc[i][5], acc[i][6], acc[i][7]);
    }

    // ---- row partial top-2: reduce over 128 columns of this tile ----
    // threads sharing trow live in the same half-warp (lanes tcol / tcol+16)
#pragma unroll
    for (int i = 0; i < 8; i++) {
        float v0 = -2.0f, v1 = -2.0f;
        int   i0 = -1,    i1 = -1;
        int cbase = m0 + tcol * 8;
#pragma unroll
        for (int j = 0; j < 8; j++)
            push2(acc[i][j], cbase + j, v0, i0, v1, i1);
#pragma unroll
        for (int off = 8; off > 0; off >>= 1) {
            float ov0 = __shfl_xor_sync(0xFFFFFFFFu, v0, off);
            float ov1 = __shfl_xor_sync(0xFFFFFFFFu, v1, off);
            int   oi0 = __shfl_xor_sync(0xFFFFFFFFu, i0, off);
            int   oi1 = __shfl_xor_sync(0xFFFFFFFFu, i1, off);
            merge2(v0, i0, v1, i1, ov0, oi0, ov1, oi1);
        }
        if (tcol == 0) {
            size_t o = ((size_t)b * NN + n0 + trow * 8 + i) * NTILES + tileM;
            g_rp_v[o] = make_float2(v0, v1);
            g_rp_i[o] = make_int2(i0, i1);
        }
    }

    // ---- col partial top-2: reduce over 128 rows of this tile ----
    // per-thread top2 over its 8 rows, per column -> smem -> 128-thread final
    __syncthreads();   // everyone done with As/Bs reads above? (k-loop done; safe to reuse)
#pragma unroll
    for (int j = 0; j < 8; j++) {
        float v0 = -2.0f, v1 = -2.0f;
        int   i0 = -1,    i1 = -1;
        int rbase = n0 + trow * 8;
#pragma unroll
        for (int i = 0; i < 8; i++)
            push2(acc[i][j], rbase + i, v0, i0, v1, i1);
        shbuf[trow * 128 + tcol * 8 + j] =
            make_float4(v0, v1, __int_as_float(i0), __int_as_float(i1));
    }
    __syncthreads();

    if (tid < 128) {
        int col = tid;
        float v0 = -2.0f, v1 = -2.0f;
        int   i0 = -1,    i1 = -1;
#pragma unroll
        for (int t = 0; t < 16; t++) {
            float4 r = shbuf[t * 128 + col];
            merge2(v0, i0, v1, i1, r.x, __float_as_int(r.z),
                                   r.y, __float_as_int(r.w));
        }
        size_t o = ((size_t)b * MM + m0 + col) * NTILES + tileN;
        g_cp_v[o] = make_float2(v0, v1);
        g_cp_i[o] = make_int2(i0, i1);
    }
}

// ---------------- 3. merge partials + thresholds ------------------------------
// one warp per row (first BB*NN warps) or per column (next BB*MM warps);
// 32 lanes <-> exactly 32 tiles.
__global__ void merge_k() {
    int warp = (blockIdx.x * blockDim.x + threadIdx.x) >> 5;
    int lane = threadIdx.x & 31;
    const int nrows = BB * NN;
    if (warp >= nrows + BB * MM) return;

    float2 pv;
    int2   pi;
    if (warp < nrows) {
        pv = g_rp_v[(size_t)warp * NTILES + lane];
        pi = g_rp_i[(size_t)warp * NTILES + lane];
    } else {
        size_t w = warp - nrows;
        pv = g_cp_v[w * NTILES + lane];
        pi = g_cp_i[w * NTILES + lane];
    }
    float v0 = pv.x, v1 = pv.y;
    int   i0 = pi.x, i1 = pi.y;
#pragma unroll
    for (int off = 16; off > 0; off >>= 1) {
        float ov0 = __shfl_xor_sync(0xFFFFFFFFu, v0, off);
        float ov1 = __shfl_xor_sync(0xFFFFFFFFu, v1, off);
        int   oi0 = __shfl_xor_sync(0xFFFFFFFFu, i0, off);
        int   oi1 = __shfl_xor_sync(0xFFFFFFFFu, i1, off);
        merge2(v0, i0, v1, i1, ov0, oi0, ov1, oi1);
    }
    if (lane == 0) {
        float d0 = 2.0f * (1.0f - v0);
        float d1 = 2.0f * (1.0f - v1);
        bool ok = (d0 <= 0.64f * d1) && (d0 <= 0.49f);
        int m = ok ? i0 : -1;
        if (warp < nrows) g_m0raw[warp] = m;
        else              g_m1raw[warp - nrows] = m;
    }
}

// ---------------- 4. mutual check + output write -----------------------------
// out layout (fp32): matches0 [B*N] | matches1 [B*M] | mscores0 | mscores1 | sim
__global__ void mutual_k(float* __restrict__ out) {
    int idx = blockIdx.x * blockDim.x + threadIdx.x;
    if (idx >= BB * NN) return;
    int b = idx / NN;
    int n = idx - b * NN;

    int m0 = g_m0raw[idx];
    bool good0 = (m0 > -1) && (g_m1raw[b * MM + m0] == n);
    out[idx] = good0 ? (float)m0 : -1.0f;
    out[2 * BB * NN + idx] = good0 ? 1.0f : 0.0f;

    int m1 = g_m1raw[idx];
    bool good1 = (m1 > -1) && (g_m0raw[b * NN + m1] == n);
    out[BB * NN + idx] = good1 ? (float)m1 : -1.0f;
    out[3 * BB * NN + idx] = good1 ? 1.0f : 0.0f;
}

// ---------------- launch -----------------------------------------------------
extern "C" void kernel_launch(void* const* d_in, const int* in_sizes, int n_in,
                              void* d_out, int out_size) {
    const float* desc0 = (const float*)d_in[0];
    const float* desc1 = (const float*)d_in[1];
    float* out = (float*)d_out;
    float* sim = out + 4 * BB * NN;

    {
        int warps = BB * NN + BB * MM;
        normalize_k<<<warps / 8, 256>>>(desc0, desc1);
    }
    {
        dim3 grid(MM / 128, NN / 128, BB);
        gemm_k<<<grid, 256>>>(sim);
    }
    {
        int warps = 2 * BB * NN;            // rows + cols
        merge_k<<<warps / 8, 256>>>();
    }
    {
        int t = BB * NN;
        mutual_k<<<(t + 255) / 256, 256>>>(out);
    }
}

// round 10
// speedup vs baseline: 1.8185x; 1.8185x over previous
#include <cuda_runtime.h>
#include <cuda_bf16.h>
#include <math.h>
#include <stdint.h>

#define BB 8
#define NN 4096
#define MM 4096
#define DD 128
#define NTILES 32          // 4096 / 128 tiles along each reduced dim

// ---------------- scratch (device globals: no allocation allowed) ----------
__device__ __nv_bfloat16 g_hi0[BB * NN * DD];
__device__ __nv_bfloat16 g_lo0[BB * NN * DD];
__device__ __nv_bfloat16 g_hi1[BB * MM * DD];
__device__ __nv_bfloat16 g_lo1[BB * MM * DD];

__device__ float2 g_rp_v[BB * NN * NTILES];
__device__ int2   g_rp_i[BB * NN * NTILES];
__device__ float2 g_cp_v[BB * MM * NTILES];
__device__ int2   g_cp_i[BB * MM * NTILES];

__device__ int    g_m0raw[BB * NN];
__device__ int    g_m1raw[BB * MM];

// ---------------- small helpers ---------------------------------------------
__device__ __forceinline__ void push2(float v, int i,
                                      float& v0, int& i0, float& v1, int& i1) {
    if (v > v0) { v1 = v0; i1 = i0; v0 = v; i0 = i; }
    else if (v > v1) { v1 = v; i1 = i; }
}

__device__ __forceinline__ bool better(float va, int ia, float vb, int ib) {
    return (va > vb) || (va == vb && ia < ib);
}

__device__ __forceinline__ void merge2(float& v0, int& i0, float& v1, int& i1,
                                       float ov0, int oi0, float ov1, int oi1) {
    if (better(ov0, oi0, v0, i0)) {
        if (better(v0, i0, ov1, oi1)) { v1 = v0; i1 = i0; }
        else                          { v1 = ov1; i1 = oi1; }
        v0 = ov0; i0 = oi0;
    } else {
        if (better(ov0, oi0, v1, i1)) { v1 = ov0; i1 = oi0; }
    }
}

__device__ __forceinline__ uint32_t smem_u32(const void* p) {
    uint32_t a;
    asm("{ .reg .u64 t; cvta.to.shared.u64 t, %1; cvt.u32.u64 %0, t; }"
        : "=r"(a) : "l"(p));
    return a;
}

__device__ __forceinline__ void ldsm_x4(uint32_t& r0, uint32_t& r1,
                                        uint32_t& r2, uint32_t& r3,
                                        uint32_t addr) {
    asm volatile(
        "ldmatrix.sync.aligned.m8n8.x4.shared.b16 {%0, %1, %2, %3}, [%4];"
        : "=r"(r0), "=r"(r1), "=r"(r2), "=r"(r3) : "r"(addr));
}

__device__ __forceinline__ void mma_bf16(float& c0, float& c1, float& c2, float& c3,
                                         uint32_t a0, uint32_t a1, uint32_t a2, uint32_t a3,
                                         uint32_t b0, uint32_t b1) {
    asm volatile(
        "mma.sync.aligned.m16n8k16.row.col.f32.bf16.bf16.f32 "
        "{%0, %1, %2, %3}, {%4, %5, %6, %7}, {%8, %9}, {%0, %1, %2, %3};"
        : "+f"(c0), "+f"(c1), "+f"(c2), "+f"(c3)
        : "r"(a0), "r"(a1), "r"(a2), "r"(a3), "r"(b0), "r"(b1));
}

// ---------------- 1. normalize + hi/lo bf16 split -----------------------------
__global__ void normsplit_k(const float* __restrict__ d0,
                            const float* __restrict__ d1) {
    int warp = (blockIdx.x * blockDim.x + threadIdx.x) >> 5;
    int lane = threadIdx.x & 31;
    const int total = BB * NN + BB * MM;
    if (warp >= total) return;

    const float* src;
    __nv_bfloat16 *hid, *lod;
    if (warp < BB * NN) {
        src = d0 + (size_t)warp * DD;
        hid = g_hi0 + (size_t)warp * DD;
        lod = g_lo0 + (size_t)warp * DD;
    } else {
        int w = warp - BB * NN;
        src = d1 + (size_t)w * DD;
        hid = g_hi1 + (size_t)w * DD;
        lod = g_lo1 + (size_t)w * DD;
    }

    float4 v = *(const float4*)(src + lane * 4);
    float s = v.x * v.x + v.y * v.y + v.z * v.z + v.w * v.w;
#pragma unroll
    for (int off = 16; off > 0; off >>= 1)
        s += __shfl_xor_sync(0xFFFFFFFFu, s, off);
    float inv = 1.0f / fmaxf(sqrtf(s), 1e-12f);

    float x[4] = { v.x * inv, v.y * inv, v.z * inv, v.w * inv };
    __nv_bfloat16 h[4], l[4];
#pragma unroll
    for (int e = 0; e < 4; e++) {
        h[e] = __float2bfloat16(x[e]);
        l[e] = __float2bfloat16(x[e] - __bfloat162float(h[e]));
    }
    ((__nv_bfloat162*)(hid + lane * 4))[0] = __nv_bfloat162(h[0], h[1]);
    ((__nv_bfloat162*)(hid + lane * 4))[1] = __nv_bfloat162(h[2], h[3]);
    ((__nv_bfloat162*)(lod + lane * 4))[0] = __nv_bfloat162(l[0], l[1]);
    ((__nv_bfloat162*)(lod + lane * 4))[1] = __nv_bfloat162(l[2], l[3]);
}

// ---------------- 2. mma.sync GEMM tile + fused top-2 -------------------------
// One CTA = one 128x128 sim tile. 256 threads = 8 warps (2 x 4), 64x32 per warp.
// K=128 in two chunks of 64 (SMEM: 4 tiles of 128 rows x 144B = 72KB -> 2 CTA/SM).
// Post-MMA, tile SMEM is reused as fp32 staging (stride 132) for col/row top-2
// reductions and the coalesced sim write.
#define KC   64            // K per chunk
#define RS   144           // bytes per smem tile row (64 bf16 = 128B + 16B pad)
#define TILE_B (128 * RS)  // 18432 B per operand tile
#define OFF_AH 0
#define OFF_AL (OFF_AH + TILE_B)
#define OFF_BH (OFF_AL + TILE_B)
#define OFF_BL (OFF_BH + TILE_B)
#define SMEM_BYTES (4 * TILE_B)   // 73728
#define DSTR 132                   // fp32 staging row stride (floats)

__global__ __launch_bounds__(256, 2)
void gemm_tc_k(float* __restrict__ C) {
    extern __shared__ char smem[];
    uint32_t sb = smem_u32(smem);

    const int b     = blockIdx.z;
    const int tileN = blockIdx.y;
    const int tileM = blockIdx.x;
    const int n0 = tileN * 128;    // sim row block   (A side, d0)
    const int m0 = tileM * 128;    // sim col block   (B side, d1)

    const int tid  = threadIdx.x;
    const int wid  = tid >> 5;
    const int lane = tid & 31;
    const int wm   = wid >> 2;     // 0..1 : 64-row band
    const int wn   = wid & 3;      // 0..3 : 32-col band
    const int g    = lane >> 2;    // group id
    const int t    = lane & 3;     // thread-in-group

    float acc[4][4][4];            // [mi][ni][c]
#pragma unroll
    for (int mi = 0; mi < 4; mi++)
#pragma unroll
        for (int ni = 0; ni < 4; ni++)
#pragma unroll
            for (int c = 0; c < 4; c++) acc[mi][ni][c] = 0.0f;

    const __nv_bfloat16* srcA_h = g_hi0 + ((size_t)b * NN + n0) * DD;
    const __nv_bfloat16* srcA_l = g_lo0 + ((size_t)b * NN + n0) * DD;
    const __nv_bfloat16* srcB_h = g_hi1 + ((size_t)b * MM + m0) * DD;
    const __nv_bfloat16* srcB_l = g_lo1 + ((size_t)b * MM + m0) * DD;

    for (int kch = 0; kch < 2; kch++) {
        const int kg = kch * KC;   // global k offset of this chunk

        // ---- load 4 operand tiles: 128 rows x 64 bf16, stride RS ----
        {
            const __nv_bfloat16* srcs[4] = { srcA_h, srcA_l, srcB_h, srcB_l };
            const int offs[4] = { OFF_AH, OFF_AL, OFF_BH, OFF_BL };
#pragma unroll
            for (int tt = 0; tt < 4; tt++) {
                const char* src = (const char*)srcs[tt];
#pragma unroll
                for (int it = 0; it < 4; it++) {
                    int f   = it * 256 + tid;   // 1024 float4 slots per tile
                    int row = f >> 3;           // 8 float4 per row
                    int q   = f & 7;
                    float4 v = *(const float4*)(src + ((size_t)row * DD + kg) * 2 + q * 16);
                    *(float4*)(smem + offs[tt] + row * RS + q * 16) = v;
                }
            }
        }
        __syncthreads();

        // ---- 3 passes x 4 k-steps of m16n8k16 ----
        const uint32_t aBase[3] = { sb + OFF_AH, sb + OFF_AL, sb + OFF_AH };
        const uint32_t bBase[3] = { sb + OFF_BH, sb + OFF_BH, sb + OFF_BL };
#pragma unroll
        for (int p = 0; p < 3; p++) {
#pragma unroll
            for (int kc = 0; kc < 4; kc++) {
                const int k0 = kc * 16;

                // A fragments: 4 x ldmatrix.x4 (rows = sim rows in this warp band)
                uint32_t a[4][4];
                {
                    int tile8 = lane >> 3;            // 0..3
                    int r8    = lane & 7;
                    int arow  = wm * 64 + (tile8 & 1) * 8 + r8;
                    int akk   = k0 + (tile8 >> 1) * 8;
                    uint32_t base = aBase[p] + akk * 2 + r8 * 0; // silence unused
#pragma unroll
                    for (int mi = 0; mi < 4; mi++) {
                        uint32_t addr = aBase[p] + (uint32_t)(arow + mi * 16) * RS + akk * 2;
                        ldsm_x4(a[mi][0], a[mi][1], a[mi][2], a[mi][3], addr);
                    }
                    (void)base;
                }

                // B fragments: 2 x ldmatrix.x4, each covering two 8-col n-frags
                uint32_t bfr[4][2];
                {
                    int tile8 = lane >> 3;            // 0..3
                    int r8    = lane & 7;
                    // tiles: [nfrag0 k0][nfrag0 k0+8][nfrag1 k0][nfrag1 k0+8]
                    int brow  = wn * 32 + ((tile8 >> 1) & 1) * 8 + r8;
                    int bkk   = k0 + (tile8 & 1) * 8;
#pragma unroll
                    for (int nh = 0; nh < 2; nh++) {
                        uint32_t addr = bBase[p] + (uint32_t)(brow + nh * 16) * RS + bkk * 2;
                        uint32_t r0, r1, r2, r3;
                        ldsm_x4(r0, r1, r2, r3, addr);
                        bfr[nh * 2 + 0][0] = r0; bfr[nh * 2 + 0][1] = r1;
                        bfr[nh * 2 + 1][0] = r2; bfr[nh * 2 + 1][1] = r3;
                    }
                }

#pragma unroll
                for (int mi = 0; mi < 4; mi++)
#pragma unroll
                    for (int ni = 0; ni < 4; ni++)
                        mma_bf16(acc[mi][ni][0], acc[mi][ni][1],
                                 acc[mi][ni][2], acc[mi][ni][3],
                                 a[mi][0], a[mi][1], a[mi][2], a[mi][3],
                                 bfr[ni][0], bfr[ni][1]);
            }
        }
        __syncthreads();   // tiles dead (or about to be reloaded)
    }

    // ---- stage accumulators to SMEM (fp32, stride DSTR) -----------------------
    float* dsm = (float*)smem;
#pragma unroll
    for (int mi = 0; mi < 4; mi++) {
        int r0 = wm * 64 + mi * 16 + g;
#pragma unroll
        for (int ni = 0; ni < 4; ni++) {
            int c0 = wn * 32 + ni * 8 + 2 * t;
            *(float2*)&dsm[r0 * DSTR + c0] =
                make_float2(acc[mi][ni][0], acc[mi][ni][1]);
            *(float2*)&dsm[(r0 + 8) * DSTR + c0] =
                make_float2(acc[mi][ni][2], acc[mi][ni][3]);
        }
    }
    __syncthreads();

    // ---- parallel reductions: threads 0-127 columns, 128-255 rows -------------
    if (tid < 128) {
        int col = tid;                       // sim column m0+col
        float v0 = -2.0f, v1 = -2.0f;
        int   i0 = -1,    i1 = -1;
#pragma unroll 4
        for (int r = 0; r < 128; r++)
            push2(dsm[r * DSTR + col], n0 + r, v0, i0, v1, i1);
        size_t o = ((size_t)b * MM + m0 + col) * NTILES + tileN;
        g_cp_v[o] = make_float2(v0, v1);
        g_cp_i[o] = make_int2(i0, i1);
    } else {
        int row = tid - 128;                 // sim row n0+row
        float v0 = -2.0f, v1 = -2.0f;
        int   i0 = -1,    i1 = -1;
#pragma unroll 4
        for (int c = 0; c < 128; c++)
            push2(dsm[row * DSTR + c], m0 + c, v0, i0, v1, i1);
        size_t o = ((size_t)b * NN + n0 + row) * NTILES + tileM;
        g_rp_v[o] = make_float2(v0, v1);
        g_rp_i[o] = make_int2(i0, i1);
    }

    // ---- coalesced sim write (float4) -----------------------------------------
    {
        float* Cb = C + (size_t)b * NN * MM + (size_t)n0 * MM + m0;
#pragma unroll
        for (int it = 0; it < 16; it++) {
            int f   = it * 256 + tid;        // 4096 float4 slots
            int row = f >> 5;                // 32 float4 per row
            int u   = f & 31;
            float4 v = *(const float4*)&dsm[row * DSTR + u * 4];
            *(float4*)(Cb + (size_t)row * MM + u * 4) = v;
        }
    }
}

// ---------------- 3. merge partials + thresholds ------------------------------
__global__ void merge_k() {
    int warp = (blockIdx.x * blockDim.x + threadIdx.x) >> 5;
    int lane = threadIdx.x & 31;
    const int nrows = BB * NN;
    if (warp >= nrows + BB * MM) return;

    float2 pv;
    int2   pi;
    if (warp < nrows) {
        pv = g_rp_v[(size_t)warp * NTILES + lane];
        pi = g_rp_i[(size_t)warp * NTILES + lane];
    } else {
        size_t w = warp - nrows;
        pv = g_cp_v[w * NTILES + lane];
        pi = g_cp_i[w * NTILES + lane];
    }
    float v0 = pv.x, v1 = pv.y;
    int   i0 = pi.x, i1 = pi.y;
#pragma unroll
    for (int off = 16; off > 0; off >>= 1) {
        float ov0 = __shfl_xor_sync(0xFFFFFFFFu, v0, off);
        float ov1 = __shfl_xor_sync(0xFFFFFFFFu, v1, off);
        int   oi0 = __shfl_xor_sync(0xFFFFFFFFu, i0, off);
        int   oi1 = __shfl_xor_sync(0xFFFFFFFFu, i1, off);
        merge2(v0, i0, v1, i1, ov0, oi0, ov1, oi1);
    }
    if (lane == 0) {
        float d0 = 2.0f * (1.0f - v0);
        float d1 = 2.0f * (1.0f - v1);
        bool ok = (d0 <= 0.64f * d1) && (d0 <= 0.49f);
        int m = ok ? i0 : -1;
        if (warp < nrows) g_m0raw[warp] = m;
        else              g_m1raw[warp - nrows] = m;
    }
}

// ---------------- 4. mutual check + output write -----------------------------
// out layout (fp32): matches0 [B*N] | matches1 [B*M] | mscores0 | mscores1 | sim
__global__ void mutual_k(float* __restrict__ out) {
    int idx = blockIdx.x * blockDim.x + threadIdx.x;
    if (idx >= BB * NN) return;
    int b = idx / NN;
    int n = idx - b * NN;

    int m0 = g_m0raw[idx];
    bool good0 = (m0 > -1) && (g_m1raw[b * MM + m0] == n);
    out[idx] = good0 ? (float)m0 : -1.0f;
    out[2 * BB * NN + idx] = good0 ? 1.0f : 0.0f;

    int m1 = g_m1raw[idx];
    bool good1 = (m1 > -1) && (g_m0raw[b * NN + m1] == n);
    out[BB * NN + idx] = good1 ? (float)m1 : -1.0f;
    out[3 * BB * NN + idx] = good1 ? 1.0f : 0.0f;
}

// ---------------- launch -----------------------------------------------------
extern "C" void kernel_launch(void* const* d_in, const int* in_sizes, int n_in,
                              void* d_out, int out_size) {
    const float* desc0 = (const float*)d_in[0];
    const float* desc1 = (const float*)d_in[1];
    float* out = (float*)d_out;
    float* sim = out + 4 * BB * NN;

    cudaFuncSetAttribute(gemm_tc_k,
                         cudaFuncAttributeMaxDynamicSharedMemorySize,
                         SMEM_BYTES);

    {
        int warps = BB * NN + BB * MM;
        normsplit_k<<<warps / 8, 256>>>(desc0, desc1);
    }
    {
        dim3 grid(MM / 128, NN / 128, BB);
        gemm_tc_k<<<grid, 256, SMEM_BYTES>>>(sim);
    }
    {
        int warps = 2 * BB * NN;
        merge_k<<<warps / 8, 256>>>();
    }
    {
        int t = BB * NN;
        mutual_k<<<(t + 255) / 256, 256>>>(out);
    }
}

// round 11
// speedup vs baseline: 2.1641x; 1.1901x over previous
#include <cuda_runtime.h>
#include <cuda_bf16.h>
#include <math.h>
#include <stdint.h>

#define BB 8
#define NN 4096
#define MM 4096
#define DD 128
#define NTILES 32          // 4096 / 128 tiles along each reduced dim

// ---------------- scratch (device globals: no allocation allowed) ----------
__device__ __nv_bfloat16 g_hi0[BB * NN * DD];
__device__ __nv_bfloat16 g_lo0[BB * NN * DD];
__device__ __nv_bfloat16 g_hi1[BB * MM * DD];
__device__ __nv_bfloat16 g_lo1[BB * MM * DD];

__device__ float2 g_rp_v[BB * NN * NTILES];
__device__ int2   g_rp_i[BB * NN * NTILES];
__device__ float2 g_cp_v[BB * MM * NTILES];
__device__ int2   g_cp_i[BB * MM * NTILES];

__device__ int    g_m0raw[BB * NN];
__device__ int    g_m1raw[BB * MM];

// ---------------- small helpers ---------------------------------------------
__device__ __forceinline__ void push2(float v, int i,
                                      float& v0, int& i0, float& v1, int& i1) {
    if (v > v0) { v1 = v0; i1 = i0; v0 = v; i0 = i; }
    else if (v > v1) { v1 = v; i1 = i; }
}

__device__ __forceinline__ bool better(float va, int ia, float vb, int ib) {
    return (va > vb) || (va == vb && ia < ib);
}

__device__ __forceinline__ void merge2(float& v0, int& i0, float& v1, int& i1,
                                       float ov0, int oi0, float ov1, int oi1) {
    if (better(ov0, oi0, v0, i0)) {
        if (better(v0, i0, ov1, oi1)) { v1 = v0; i1 = i0; }
        else                          { v1 = ov1; i1 = oi1; }
        v0 = ov0; i0 = oi0;
    } else {
        if (better(ov0, oi0, v1, i1)) { v1 = ov0; i1 = oi0; }
    }
}

__device__ __forceinline__ uint32_t smem_u32(const void* p) {
    uint32_t a;
    asm("{ .reg .u64 t; cvta.to.shared.u64 t, %1; cvt.u32.u64 %0, t; }"
        : "=r"(a) : "l"(p));
    return a;
}

__device__ __forceinline__ void ldsm_x4(uint32_t& r0, uint32_t& r1,
                                        uint32_t& r2, uint32_t& r3,
                                        uint32_t addr) {
    asm volatile(
        "ldmatrix.sync.aligned.m8n8.x4.shared.b16 {%0, %1, %2, %3}, [%4];"
        : "=r"(r0), "=r"(r1), "=r"(r2), "=r"(r3) : "r"(addr));
}

__device__ __forceinline__ void mma_bf16(float& c0, float& c1, float& c2, float& c3,
                                         uint32_t a0, uint32_t a1, uint32_t a2, uint32_t a3,
                                         uint32_t b0, uint32_t b1) {
    asm volatile(
        "mma.sync.aligned.m16n8k16.row.col.f32.bf16.bf16.f32 "
        "{%0, %1, %2, %3}, {%4, %5, %6, %7}, {%8, %9}, {%0, %1, %2, %3};"
        : "+f"(c0), "+f"(c1), "+f"(c2), "+f"(c3)
        : "r"(a0), "r"(a1), "r"(a2), "r"(a3), "r"(b0), "r"(b1));
}

__device__ __forceinline__ void cp_async16(uint32_t saddr, const void* gaddr) {
    asm volatile("cp.async.cg.shared.global [%0], [%1], 16;"
                 :: "r"(saddr), "l"(gaddr));
}
#define CP_COMMIT() asm volatile("cp.async.commit_group;" ::: "memory")
#define CP_WAIT0()  asm volatile("cp.async.wait_group 0;" ::: "memory")

// ---------------- 1. normalize + hi/lo bf16 split -----------------------------
__global__ void normsplit_k(const float* __restrict__ d0,
                            const float* __restrict__ d1) {
    int warp = (blockIdx.x * blockDim.x + threadIdx.x) >> 5;
    int lane = threadIdx.x & 31;
    const int total = BB * NN + BB * MM;
    if (warp >= total) return;

    const float* src;
    __nv_bfloat16 *hid, *lod;
    if (warp < BB * NN) {
        src = d0 + (size_t)warp * DD;
        hid = g_hi0 + (size_t)warp * DD;
        lod = g_lo0 + (size_t)warp * DD;
    } else {
        int w = warp - BB * NN;
        src = d1 + (size_t)w * DD;
        hid = g_hi1 + (size_t)w * DD;
        lod = g_lo1 + (size_t)w * DD;
    }

    float4 v = *(const float4*)(src + lane * 4);
    float s = v.x * v.x + v.y * v.y + v.z * v.z + v.w * v.w;
#pragma unroll
    for (int off = 16; off > 0; off >>= 1)
        s += __shfl_xor_sync(0xFFFFFFFFu, s, off);
    float inv = 1.0f / fmaxf(sqrtf(s), 1e-12f);

    float x[4] = { v.x * inv, v.y * inv, v.z * inv, v.w * inv };
    __nv_bfloat16 h[4], l[4];
#pragma unroll
    for (int e = 0; e < 4; e++) {
        h[e] = __float2bfloat16(x[e]);
        l[e] = __float2bfloat16(x[e] - __bfloat162float(h[e]));
    }
    ((__nv_bfloat162*)(hid + lane * 4))[0] = __nv_bfloat162(h[0], h[1]);
    ((__nv_bfloat162*)(hid + lane * 4))[1] = __nv_bfloat162(h[2], h[3]);
    ((__nv_bfloat162*)(lod + lane * 4))[0] = __nv_bfloat162(l[0], l[1]);
    ((__nv_bfloat162*)(lod + lane * 4))[1] = __nv_bfloat162(l[2], l[3]);
}

// ---------------- 2. mma.sync GEMM tile + fused top-2 -------------------------
// One CTA = one 128x128 sim tile. 256 threads = 8 warps (2 x 4), 64x32 per warp.
// K=128 in two chunks of 64 (SMEM: 4 tiles of 128 rows x 144B = 72KB -> 2 CTA/SM).
// Per k-step, fragments are loaded ONCE and shared across the 3 precision
// passes: hi*hi, hi*lo, lo*hi (12 ldsm.x4 for 48 MMAs).
#define KC   64            // K per chunk
#define RS   144           // bytes per smem tile row (64 bf16 = 128B + 16B pad)
#define TILE_B (128 * RS)  // 18432 B per operand tile
#define OFF_AH 0
#define OFF_AL (OFF_AH + TILE_B)
#define OFF_BH (OFF_AL + TILE_B)
#define OFF_BL (OFF_BH + TILE_B)
#define SMEM_BYTES (4 * TILE_B)   // 73728
#define DSTR 130                   // fp32 staging row stride (floats)

__global__ __launch_bounds__(256, 2)
void gemm_tc_k(float* __restrict__ C) {
    extern __shared__ char smem[];
    uint32_t sb = smem_u32(smem);

    const int b     = blockIdx.z;
    const int tileN = blockIdx.y;
    const int tileM = blockIdx.x;
    const int n0 = tileN * 128;    // sim row block   (A side, d0)
    const int m0 = tileM * 128;    // sim col block   (B side, d1)

    const int tid  = threadIdx.x;
    const int wid  = tid >> 5;
    const int lane = tid & 31;
    const int wm   = wid >> 2;     // 0..1 : 64-row band
    const int wn   = wid & 3;      // 0..3 : 32-col band
    const int g    = lane >> 2;    // group id
    const int t    = lane & 3;     // thread-in-group
    const int tile8 = lane >> 3;
    const int r8    = lane & 7;

    // lane-constant ldmatrix offsets (bytes) within a tile
    const uint32_t aoff = (uint32_t)(wm * 64 + (tile8 & 1) * 8 + r8) * RS
                        + (uint32_t)((tile8 >> 1) * 8) * 2;
    const uint32_t boff = (uint32_t)(wn * 32 + ((tile8 >> 1) & 1) * 8 + r8) * RS
                        + (uint32_t)((tile8 & 1) * 8) * 2;

    float acc[4][4][4];            // [mi][ni][c]
#pragma unroll
    for (int mi = 0; mi < 4; mi++)
#pragma unroll
        for (int ni = 0; ni < 4; ni++)
#pragma unroll
            for (int c = 0; c < 4; c++) acc[mi][ni][c] = 0.0f;

    const char* srcs[4] = {
        (const char*)(g_hi0 + ((size_t)b * NN + n0) * DD),
        (const char*)(g_lo0 + ((size_t)b * NN + n0) * DD),
        (const char*)(g_hi1 + ((size_t)b * MM + m0) * DD),
        (const char*)(g_lo1 + ((size_t)b * MM + m0) * DD)
    };
    const int offs[4] = { OFF_AH, OFF_AL, OFF_BH, OFF_BL };

    for (int kch = 0; kch < 2; kch++) {
        const int kg = kch * KC;   // global k offset of this chunk

        // ---- async load: 4 tiles x 128 rows x 64 bf16 (stride RS) ----
#pragma unroll
        for (int tt = 0; tt < 4; tt++) {
#pragma unroll
            for (int it = 0; it < 4; it++) {
                int f   = it * 256 + tid;   // 1024 16B slots per tile
                int row = f >> 3;           // 8 slots per row
                int q   = f & 7;
                cp_async16(sb + offs[tt] + row * RS + q * 16,
                           srcs[tt] + ((size_t)row * DD + kg) * 2 + q * 16);
            }
        }
        CP_COMMIT();
        CP_WAIT0();
        __syncthreads();

        // ---- 4 k-steps; fragments shared across the 3 precision passes ----
#pragma unroll
        for (int kc = 0; kc < 4; kc++) {
            const uint32_t kb = kc * 32;   // byte offset of this k-step

            // A_hi fragments
            uint32_t a[4][4];
#pragma unroll
            for (int mi = 0; mi < 4; mi++)
                ldsm_x4(a[mi][0], a[mi][1], a[mi][2], a[mi][3],
                        sb + OFF_AH + aoff + mi * (16 * RS) + kb);

            // B_hi fragments
            uint32_t bh[4][2];
#pragma unroll
            for (int nh = 0; nh < 2; nh++) {
                uint32_t r0, r1, r2, r3;
                ldsm_x4(r0, r1, r2, r3,
                        sb + OFF_BH + boff + nh * (16 * RS) + kb);
                bh[nh * 2 + 0][0] = r0; bh[nh * 2 + 0][1] = r1;
                bh[nh * 2 + 1][0] = r2; bh[nh * 2 + 1][1] = r3;
            }

            // pass 0: hi * hi
#pragma unroll
            for (int mi = 0; mi < 4; mi++)
#pragma unroll
                for (int ni = 0; ni < 4; ni++)
                    mma_bf16(acc[mi][ni][0], acc[mi][ni][1],
                             acc[mi][ni][2], acc[mi][ni][3],
                             a[mi][0], a[mi][1], a[mi][2], a[mi][3],
                             bh[ni][0], bh[ni][1]);

            // B_lo fragments
            uint32_t bl[4][2];
#pragma unroll
            for (int nh = 0; nh < 2; nh++) {
                uint32_t r0, r1, r2, r3;
                ldsm_x4(r0, r1, r2, r3,
                        sb + OFF_BL + boff + nh * (16 * RS) + kb);
                bl[nh * 2 + 0][0] = r0; bl[nh * 2 + 0][1] = r1;
                bl[nh * 2 + 1][0] = r2; bl[nh * 2 + 1][1] = r3;
            }

            // pass 1: hi * lo
#pragma unroll
            for (int mi = 0; mi < 4; mi++)
#pragma unroll
                for (int ni = 0; ni < 4; ni++)
                    mma_bf16(acc[mi][ni][0], acc[mi][ni][1],
                             acc[mi][ni][2], acc[mi][ni][3],
                             a[mi][0], a[mi][1], a[mi][2], a[mi][3],
                             bl[ni][0], bl[ni][1]);

            // A_lo fragments (reuse a[])
#pragma unroll
            for (int mi = 0; mi < 4; mi++)
                ldsm_x4(a[mi][0], a[mi][1], a[mi][2], a[mi][3],
                        sb + OFF_AL + aoff + mi * (16 * RS) + kb);

            // pass 2: lo * hi
#pragma unroll
            for (int mi = 0; mi < 4; mi++)
#pragma unroll
                for (int ni = 0; ni < 4; ni++)
                    mma_bf16(acc[mi][ni][0], acc[mi][ni][1],
                             acc[mi][ni][2], acc[mi][ni][3],
                             a[mi][0], a[mi][1], a[mi][2], a[mi][3],
                             bh[ni][0], bh[ni][1]);
        }
        __syncthreads();   // tiles dead before next chunk's cp.async / staging
    }

    // ---- stage accumulators to SMEM (fp32, stride DSTR) -----------------------
    float* dsm = (float*)smem;
#pragma unroll
    for (int mi = 0; mi < 4; mi++) {
        int r0 = wm * 64 + mi * 16 + g;
#pragma unroll
        for (int ni = 0; ni < 4; ni++) {
            int c0 = wn * 32 + ni * 8 + 2 * t;
            *(float2*)&dsm[r0 * DSTR + c0] =
                make_float2(acc[mi][ni][0], acc[mi][ni][1]);
            *(float2*)&dsm[(r0 + 8) * DSTR + c0] =
                make_float2(acc[mi][ni][2], acc[mi][ni][3]);
        }
    }
    __syncthreads();

    // ---- parallel reductions: threads 0-127 columns, 128-255 rows -------------
    if (tid < 128) {
        int col = tid;                       // sim column m0+col
        float v0 = -2.0f, v1 = -2.0f;
        int   i0 = -1,    i1 = -1;
#pragma unroll 4
        for (int r = 0; r < 128; r++)
            push2(dsm[r * DSTR + col], n0 + r, v0, i0, v1, i1);
        size_t o = ((size_t)b * MM + m0 + col) * NTILES + tileN;
        g_cp_v[o] = make_float2(v0, v1);
        g_cp_i[o] = make_int2(i0, i1);
    } else {
        int row = tid - 128;                 // sim row n0+row
        float v0 = -2.0f, v1 = -2.0f;
        int   i0 = -1,    i1 = -1;
#pragma unroll 4
        for (int c = 0; c < 128; c += 2) {
            float2 v = *(const float2*)&dsm[row * DSTR + c];
            push2(v.x, m0 + c,     v0, i0, v1, i1);
            push2(v.y, m0 + c + 1, v0, i0, v1, i1);
        }
        size_t o = ((size_t)b * NN + n0 + row) * NTILES + tileM;
        g_rp_v[o] = make_float2(v0, v1);
        g_rp_i[o] = make_int2(i0, i1);
    }

    // ---- coalesced sim write (float2) -----------------------------------------
    {
        float* Cb = C + (size_t)b * NN * MM + (size_t)n0 * MM + m0;
#pragma unroll
        for (int it = 0; it < 32; it++) {
            int f   = it * 256 + tid;        // 8192 float2 slots
            int row = f >> 6;                // 64 float2 per row
            int u   = f & 63;
            float2 v = *(const float2*)&dsm[row * DSTR + u * 2];
            *(float2*)(Cb + (size_t)row * MM + u * 2) = v;
        }
    }
}

// ---------------- 3. merge partials + thresholds ------------------------------
__global__ void merge_k() {
    int warp = (blockIdx.x * blockDim.x + threadIdx.x) >> 5;
    int lane = threadIdx.x & 31;
    const int nrows = BB * NN;
    if (warp >= nrows + BB * MM) return;

    float2 pv;
    int2   pi;
    if (warp < nrows) {
        pv = g_rp_v[(size_t)warp * NTILES + lane];
        pi = g_rp_i[(size_t)warp * NTILES + lane];
    } else {
        size_t w = warp - nrows;
        pv = g_cp_v[w * NTILES + lane];
        pi = g_cp_i[w * NTILES + lane];
    }
    float v0 = pv.x, v1 = pv.y;
    int   i0 = pi.x, i1 = pi.y;
#pragma unroll
    for (int off = 16; off > 0; off >>= 1) {
        float ov0 = __shfl_xor_sync(0xFFFFFFFFu, v0, off);
        float ov1 = __shfl_xor_sync(0xFFFFFFFFu, v1, off);
        int   oi0 = __shfl_xor_sync(0xFFFFFFFFu, i0, off);
        int   oi1 = __shfl_xor_sync(0xFFFFFFFFu, i1, off);
        merge2(v0, i0, v1, i1, ov0, oi0, ov1, oi1);
    }
    if (lane == 0) {
        float d0 = 2.0f * (1.0f - v0);
        float d1 = 2.0f * (1.0f - v1);
        bool ok = (d0 <= 0.64f * d1) && (d0 <= 0.49f);
        int m = ok ? i0 : -1;
        if (warp < nrows) g_m0raw[warp] = m;
        else              g_m1raw[warp - nrows] = m;
    }
}

// ---------------- 4. mutual check + output write -----------------------------
// out layout (fp32): matches0 [B*N] | matches1 [B*M] | mscores0 | mscores1 | sim
__global__ void mutual_k(float* __restrict__ out) {
    int idx = blockIdx.x * blockDim.x + threadIdx.x;
    if (idx >= BB * NN) return;
    int b = idx / NN;
    int n = idx - b * NN;

    int m0 = g_m0raw[idx];
    bool good0 = (m0 > -1) && (g_m1raw[b * MM + m0] == n);
    out[idx] = good0 ? (float)m0 : -1.0f;
    out[2 * BB * NN + idx] = good0 ? 1.0f : 0.0f;

    int m1 = g_m1raw[idx];
    bool good1 = (m1 > -1) && (g_m0raw[b * NN + m1] == n);
    out[BB * NN + idx] = good1 ? (float)m1 : -1.0f;
    out[3 * BB * NN + idx] = good1 ? 1.0f : 0.0f;
}

// ---------------- launch -----------------------------------------------------
extern "C" void kernel_launch(void* const* d_in, const int* in_sizes, int n_in,
                              void* d_out, int out_size) {
    const float* desc0 = (const float*)d_in[0];
    const float* desc1 = (const float*)d_in[1];
    float* out = (float*)d_out;
    float* sim = out + 4 * BB * NN;

    cudaFuncSetAttribute(gemm_tc_k,
                         cudaFuncAttributeMaxDynamicSharedMemorySize,
                         SMEM_BYTES);

    {
        int warps = BB * NN + BB * MM;
        normsplit_k<<<warps / 8, 256>>>(desc0, desc1);
    }
    {
        dim3 grid(MM / 128, NN / 128, BB);
        gemm_tc_k<<<grid, 256, SMEM_BYTES>>>(sim);
    }
    {
        int warps = 2 * BB * NN;
        merge_k<<<warps / 8, 256>>>();
    }
    {
        int t = BB * NN;
        mutual_k<<<(t + 255) / 256, 256>>>(out);
    }
}